// round 14
// baseline (speedup 1.0000x reference)
#include <cuda_runtime.h>
#include <cstddef>

// ---------------------------------------------------------------------------
// RBFolution: out[b,oh,ow,f] = exp(-beta[f] * (||p||^2 - 2 p.ccs[:,f] + ||c_f||^2))
// B=32,H=W=112,C=32,F=128,D=288, valid 3x3 -> Ho=Wo=110.
//
// R13: packed-FFMA2 mainloop. Evidence: two different kernels both pinned at
// fma=~50% / issue=~57% -> FFMA-3reg rt_SMSP=2 ceiling (RF banking). Escape:
// PTX fma.rn.f32x2 = 2 FMAs per issue slot, same fp32 rounding.
//
// Block: 256 threads, tile 16x8 pixels x 64 filters (F-split, 2 blocks/SM).
//   fid  = tid & 3        -> filters g*16 + fid*4 .. +3, g = 0..3
//   prow = (tid>>2) & 15  -> pixel row in tile
//   pcg  = tid >> 6       -> pixel column pair (2 cols each)
// Per thread: 2 px x 16 filters = 16 packed f32x2 accumulators.
// ---------------------------------------------------------------------------

#define Bn 32
#define Hn 112
#define Wn 112
#define Cn 32
#define Fn 128
#define FHALF 64
#define HoN 110
#define WoN 110
#define Dn 288            // 3*3*Cn

#define TILE_H 16
#define TILE_W 8
#define THREADS 256

#define XS_H (TILE_H + 2)         // 18
#define XS_W (TILE_W + 2)         // 10
#define XS_RPITCH (XS_W * Cn + 4) // 324 floats: row stride = 16B mod 128B -> A conflict-free

#define SMEM_FLOATS (Dn * FHALF + XS_H * XS_RPITCH + TILE_H * TILE_W + FHALF + FHALF)
#define SMEM_BYTES (SMEM_FLOATS * 4)

// packed f32x2 FMA: d = a*b + d elementwise on {lo,hi}
#define FMA2(d, a, b) \
    asm("fma.rn.f32x2 %0, %1, %2, %0;" : "+l"(d) : "l"(a), "l"(b))
// splat one fp32 into both lanes of an f32x2
#define SPLAT2(d, s) \
    asm("mov.b64 %0, {%1, %1};" : "=l"(d) : "f"(s))
// unpack f32x2 -> two fp32
#define UNPACK2(lo, hi, s) \
    asm("mov.b64 {%0, %1}, %2;" : "=f"(lo), "=f"(hi) : "l"(s))

__global__ void __launch_bounds__(THREADS, 2)
rbfolution_kernel(const float* __restrict__ x,
                  const float* __restrict__ ccs,
                  const float* __restrict__ beta,
                  float* __restrict__ out)
{
    extern __shared__ float smem[];
    float* sccs  = smem;                         // [Dn][FHALF]   73728 B
    float* xs    = sccs + Dn * FHALF;            // [XS_H][XS_RPITCH]  23328 B
    float* psq   = xs + XS_H * XS_RPITCH;        // [128] per-pixel ||p||^2
    float* csq   = psq + TILE_H * TILE_W;        // [64] per-filter ||c||^2
    float* sbeta = csq + FHALF;                  // [64]

    const int tid = threadIdx.x;
    const int bz  = blockIdx.z;
    const int b   = bz >> 1;
    const int fh  = bz & 1;                      // filter half: 0 or 1
    const int oh0 = blockIdx.y * TILE_H;
    const int ow0 = blockIdx.x * TILE_W;

    // ---- load this block's 64-filter slice of ccs into smem ----
    {
        const float4* src = reinterpret_cast<const float4*>(ccs);
        float4* dst = reinterpret_cast<float4*>(sccs);
        const int fh16 = fh * (FHALF / 4);
        #pragma unroll
        for (int it = 0; it < (Dn * FHALF / 4) / THREADS; ++it) {  // 18 iters
            int i = tid + it * THREADS;
            int d = i >> 4;
            int v = i & 15;
            dst[i] = src[d * (Fn / 4) + fh16 + v];
        }
    }

    // ---- load x halo tile (18 x 10 x 32), zero-fill out-of-bounds ----
    {
        const int NV = XS_H * XS_W * (Cn / 4);   // 1440 float4 slots (logical)
        for (int i = tid; i < NV; i += THREADS) {
            int pos = i / (Cn / 4);
            int v   = i % (Cn / 4);
            int r   = pos / XS_W;
            int col = pos % XS_W;
            int gr  = oh0 + r;
            int gc  = ow0 + col;
            float4 val = make_float4(0.f, 0.f, 0.f, 0.f);
            if (gr < Hn && gc < Wn) {
                val = *reinterpret_cast<const float4*>(
                    x + (((size_t)b * Hn + gr) * Wn + gc) * Cn + v * 4);
            }
            float* d = xs + r * XS_RPITCH + col * Cn + v * 4;
            d[0] = val.x; d[1] = val.y; d[2] = val.z; d[3] = val.w;
        }
    }
    __syncthreads();

    // ---- threads 0-127: per-pixel ||p||^2 ; threads 128-191: ||c||^2 + beta ----
    if (tid < TILE_H * TILE_W) {
        const int ty = tid >> 3;
        const int tx = tid & 7;
        float s = 0.f;
        #pragma unroll
        for (int tr = 0; tr < 3; ++tr) {
            #pragma unroll
            for (int tc = 0; tc < 3; ++tc) {
                const float* p = xs + (ty + tr) * XS_RPITCH + (tx + tc) * Cn;
                #pragma unroll
                for (int c = 0; c < Cn; ++c) {
                    float v = p[c];
                    s = fmaf(v, v, s);
                }
            }
        }
        psq[tid] = s;
    } else if (tid < 128 + FHALF) {
        const int f = tid - 128;
        float s = 0.f;
        #pragma unroll 8
        for (int d = 0; d < Dn; ++d) {
            float v = sccs[d * FHALF + f];
            s = fmaf(v, v, s);
        }
        csq[f] = s;
        sbeta[f] = beta[fh * FHALF + f];
    }
    __syncthreads();

    // ---- main loop: packed acc[px][pair] over 2 px x 16 filters ----
    const int fid  = tid & 3;          // 4 filter groups; thread owns g*16+fid*4..+3
    const int prow = (tid >> 2) & 15;  // pixel row within tile
    const int pcg  = tid >> 6;         // pixel column pair (0..3)

    unsigned long long acc[2][8];      // [px][pair]: pair p of group g at index g*2+(p&1)
    #pragma unroll
    for (int i = 0; i < 2; ++i)
        #pragma unroll
        for (int j = 0; j < 8; ++j)
            acc[i][j] = 0ULL;

    #pragma unroll 1
    for (int tr = 0; tr < 3; ++tr) {
        #pragma unroll 1
        for (int tc = 0; tc < 3; ++tc) {
            const float* ap = xs + (prow + tr) * XS_RPITCH + (pcg * 2 + tc) * Cn;
            const float* bp = sccs + (size_t)(tr * 3 + tc) * Cn * FHALF + fid * 4;
            #pragma unroll 2
            for (int c4 = 0; c4 < Cn / 4; ++c4) {
                float a0[4], a1[4];
                *reinterpret_cast<float4*>(a0) =
                    *reinterpret_cast<const float4*>(ap + c4 * 4);
                *reinterpret_cast<float4*>(a1) =
                    *reinterpret_cast<const float4*>(ap + Cn + c4 * 4);
                #pragma unroll
                for (int cc = 0; cc < 4; ++cc) {
                    unsigned long long pa0, pa1;
                    SPLAT2(pa0, a0[cc]);
                    SPLAT2(pa1, a1[cc]);
                    const float* brow = bp + (c4 * 4 + cc) * FHALF;
                    #pragma unroll
                    for (int g = 0; g < 4; ++g) {
                        // 16B load -> two f32x2 pairs (filters g*16+fid*4 .. +3)
                        const ulonglong2 bv =
                            *reinterpret_cast<const ulonglong2*>(brow + g * 16);
                        FMA2(acc[0][g * 2 + 0], pa0, bv.x);
                        FMA2(acc[0][g * 2 + 1], pa0, bv.y);
                        FMA2(acc[1][g * 2 + 0], pa1, bv.x);
                        FMA2(acc[1][g * 2 + 1], pa1, bv.y);
                    }
                }
            }
        }
    }

    // ---- epilogue: score = psq + csq - 2*dot ; out = exp(-beta*score) ----
    const int oh = oh0 + prow;
    if (oh < HoN) {
        #pragma unroll
        for (int px = 0; px < 2; ++px) {
            const int ow = ow0 + pcg * 2 + px;
            if (ow < WoN) {
                const float ps = psq[prow * TILE_W + pcg * 2 + px];
                float* op = out + (((size_t)b * HoN + oh) * WoN + ow) * Fn
                                + fh * FHALF;
                #pragma unroll
                for (int g = 0; g < 4; ++g) {
                    const int f0 = g * 16 + fid * 4;
                    float d0, d1, d2, d3;
                    UNPACK2(d0, d1, acc[px][g * 2 + 0]);
                    UNPACK2(d2, d3, acc[px][g * 2 + 1]);
                    float4 r;
                    r.x = __expf(-sbeta[f0 + 0] * (ps + csq[f0 + 0] - 2.f * d0));
                    r.y = __expf(-sbeta[f0 + 1] * (ps + csq[f0 + 1] - 2.f * d1));
                    r.z = __expf(-sbeta[f0 + 2] * (ps + csq[f0 + 2] - 2.f * d2));
                    r.w = __expf(-sbeta[f0 + 3] * (ps + csq[f0 + 3] - 2.f * d3));
                    *reinterpret_cast<float4*>(op + f0) = r;
                }
            }
        }
    }
}

extern "C" void kernel_launch(void* const* d_in, const int* in_sizes, int n_in,
                              void* d_out, int out_size)
{
    (void)in_sizes; (void)n_in; (void)out_size;
    const float* x    = (const float*)d_in[0];
    const float* ccs  = (const float*)d_in[1];
    const float* beta = (const float*)d_in[2];
    float* out = (float*)d_out;

    cudaFuncSetAttribute(rbfolution_kernel,
                         cudaFuncAttributeMaxDynamicSharedMemorySize, SMEM_BYTES);

    dim3 grid((WoN + TILE_W - 1) / TILE_W,   // 14
              (HoN + TILE_H - 1) / TILE_H,   // 7
              Bn * 2);                       // 32 batches x 2 filter halves
    rbfolution_kernel<<<grid, THREADS, SMEM_BYTES>>>(x, ccs, beta, out);
}

// round 16
// speedup vs baseline: 2.4048x; 2.4048x over previous
#include <cuda_runtime.h>
#include <cuda_bf16.h>
#include <cstdint>
#include <cstddef>

// ---------------------------------------------------------------------------
// RBFolution via legacy tensor-core mma.sync (bf16, split 3-pass), sm_103-safe
// (no 'a'-suffix ISA: harness compiles through virtual compute_103).
//
//   out[b,oh,ow,f] = exp(-beta[f] * (||p||^2 - 2 p.c_f + ||c_f||^2))
//   B=32,H=W=112,C=32,F=128,D=288 -> Ho=Wo=110.
//
// dot[px,f] = A[px,:].Bm[f,:],  Bm = -2*ccs^T, K=288 = 18 steps of k16.
// Split bf16: v = hi + lo; dot ~= Ah.Bh + Al.Bh + Ah.Bl (Al.Bl dropped,
// ~2^-18/term -> |dscore| ~1e-4 << 1e-3 budget). psq/csq in full fp32.
//
// CTA: 256 thr (8 warps), tile 16x8 px x 128 f. Warp w owns px [16w,16w+16).
// A: split-bf16 halo tile in smem (pixel pitch 40 elems -> ldmatrix rows hit
//    8 distinct banks); im2col done in ldmatrix lane addressing. No staging.
// B: split, pre-built by prep kernel in gmem, copied to smem (row pitch 592B
//    -> conflict-free ldmatrix).
// ---------------------------------------------------------------------------

#define Bn 32
#define Hn 112
#define Wn 112
#define Cn 32
#define Fn 128
#define HoN 110
#define WoN 110
#define Dn 288

#define TILE_H 16
#define TILE_W 8
#define THREADS 256

// B smem: [2 halves][128 f][pitch 296 bf16] ; 592B rows
#define B_PITCH   296
#define B_ROW_B   (B_PITCH * 2)              // 592
#define B_HALF_B  (Fn * B_ROW_B)             // 75776
// halo: [18][10] px, pixel pitch 40 bf16 (80B)
#define PX_PITCH  40
#define HALO_B    (18 * 10 * PX_PITCH * 2)   // 14400

#define SM_B      0
#define SM_XH     (2 * B_HALF_B)             // 151552
#define SM_XL     (SM_XH + HALO_B)           // 165952
#define SM_PSQ    (SM_XL + HALO_B)           // 180352
#define SM_CSQ    (SM_PSQ + 512)
#define SM_BETA   (SM_CSQ + 512)
#define SM_END    (SM_BETA + 512)            // 181888
#define SMEM_BYTES (SM_END + 1024)

#define LDSM_X4(r, addr) \
    asm volatile("ldmatrix.sync.aligned.m8n8.x4.shared.b16 {%0,%1,%2,%3}, [%4];" \
        : "=r"((r)[0]), "=r"((r)[1]), "=r"((r)[2]), "=r"((r)[3]) : "r"(addr))

#define MMA_BF16(c, a, b0, b1) \
    asm volatile("mma.sync.aligned.m16n8k16.row.col.f32.bf16.bf16.f32 " \
        "{%0,%1,%2,%3}, {%4,%5,%6,%7}, {%8,%9}, {%0,%1,%2,%3};" \
        : "+f"((c)[0]), "+f"((c)[1]), "+f"((c)[2]), "+f"((c)[3]) \
        : "r"((a)[0]), "r"((a)[1]), "r"((a)[2]), "r"((a)[3]), "r"(b0), "r"(b1))

__device__ __forceinline__ uint32_t smem_to_u32(const void* p) {
    uint32_t a;
    asm("{ .reg .u64 t; cvta.to.shared.u64 t, %1; cvt.u32.u64 %0, t; }" : "=r"(a) : "l"(p));
    return a;
}

// ---- device globals (no runtime allocation allowed) ----
// gB layout: [half][f][k] bf16, contiguous k=288
__device__ __align__(16) __nv_bfloat16 gB[2 * Fn * Dn];
__device__ float gcsq[Fn];

// ===========================================================================
// Prep: Bm = -2*ccs^T split into (hi, lo); csq[f] = sum_d ccs[d][f]^2.
// Grid: 145 blocks x 256 (blocks 0..143: 36864 B elems; block 144: csq).
// ===========================================================================
__global__ void rbf_prep_kernel(const float* __restrict__ ccs)
{
    if (blockIdx.x == 144) {
        int f = threadIdx.x;
        if (f < Fn) {
            float s = 0.f;
            for (int d = 0; d < Dn; ++d) {
                float v = ccs[d * Fn + f];
                s = fmaf(v, v, s);
            }
            gcsq[f] = s;
        }
        return;
    }
    int idx = blockIdx.x * 256 + threadIdx.x;   // < 36864 = 128*288
    int f = idx / Dn;
    int k = idx - f * Dn;
    float val = -2.0f * ccs[k * Fn + f];
    __nv_bfloat16 h = __float2bfloat16(val);
    __nv_bfloat16 l = __float2bfloat16(val - __bfloat162float(h));
    gB[f * Dn + k] = h;
    gB[Fn * Dn + f * Dn + k] = l;
}

// ===========================================================================
// Main kernel
// ===========================================================================
__global__ void __launch_bounds__(THREADS, 1)
rbf_mma_kernel(const float* __restrict__ x,
               const float* __restrict__ beta,
               float* __restrict__ out)
{
    extern __shared__ char smraw[];
    const uint32_t base_raw = smem_to_u32(smraw);
    const uint32_t base = (base_raw + 1023) & ~1023u;
    char* sm = smraw + (base - base_raw);

    const int tid = threadIdx.x;
    const int wid = tid >> 5;
    const int lid = tid & 31;
    const int b   = blockIdx.z;
    const int oh0 = blockIdx.y * TILE_H;
    const int ow0 = blockIdx.x * TILE_W;

    float* psq   = reinterpret_cast<float*>(sm + SM_PSQ);
    float* csq   = reinterpret_cast<float*>(sm + SM_CSQ);
    float* sbeta = reinterpret_cast<float*>(sm + SM_BETA);

    // ---- copy split-B gmem -> smem with pitch expansion (9216 x 16B) ----
    {
        const float4* src = reinterpret_cast<const float4*>(gB);
        #pragma unroll 4
        for (int i = tid; i < 9216; i += THREADS) {
            int half = i / 4608;
            int rem  = i - half * 4608;
            int r    = rem / 36;            // 36 float4 per 288-elem row
            int v    = rem - r * 36;
            *reinterpret_cast<float4*>(sm + SM_B + half * B_HALF_B + r * B_ROW_B + v * 16)
                = src[i];
        }
    }

    // ---- load + split halo tile (18x10x32) into xh/xl ----
    {
        for (int i = tid; i < 1440; i += THREADS) {     // 1440 float4 = 5760 elems
            int pos = i >> 3;
            int v   = i & 7;
            int r   = pos / 10;
            int col = pos - r * 10;
            int gr  = oh0 + r, gc = ow0 + col;
            float4 val = make_float4(0.f, 0.f, 0.f, 0.f);
            if (gr < Hn && gc < Wn)
                val = *reinterpret_cast<const float4*>(
                    x + (((size_t)b * Hn + gr) * Wn + gc) * Cn + v * 4);
            __nv_bfloat16 h0 = __float2bfloat16(val.x), h1 = __float2bfloat16(val.y);
            __nv_bfloat16 h2 = __float2bfloat16(val.z), h3 = __float2bfloat16(val.w);
            __nv_bfloat16 l0 = __float2bfloat16(val.x - __bfloat162float(h0));
            __nv_bfloat16 l1 = __float2bfloat16(val.y - __bfloat162float(h1));
            __nv_bfloat16 l2 = __float2bfloat16(val.z - __bfloat162float(h2));
            __nv_bfloat16 l3 = __float2bfloat16(val.w - __bfloat162float(h3));
            uint2 hw, lw;
            hw.x = ((uint32_t)__bfloat16_as_ushort(h1) << 16) | __bfloat16_as_ushort(h0);
            hw.y = ((uint32_t)__bfloat16_as_ushort(h3) << 16) | __bfloat16_as_ushort(h2);
            lw.x = ((uint32_t)__bfloat16_as_ushort(l1) << 16) | __bfloat16_as_ushort(l0);
            lw.y = ((uint32_t)__bfloat16_as_ushort(l3) << 16) | __bfloat16_as_ushort(l2);
            const int off = ((r * 10 + col) * PX_PITCH + v * 4) * 2;
            *reinterpret_cast<uint2*>(sm + SM_XH + off) = hw;
            *reinterpret_cast<uint2*>(sm + SM_XL + off) = lw;
        }
    }

    // ---- psq (threads 0..127, fp32 from gmem) ; csq/beta (128..255) ----
    if (tid < 128) {
        const int prow = tid >> 3, pcol = tid & 7;
        float s = 0.f;
        #pragma unroll
        for (int pos = 0; pos < 9; ++pos) {
            const int tr = pos / 3, tc = pos % 3;
            const int gr = oh0 + prow + tr, gc = ow0 + pcol + tc;
            if (gr < Hn && gc < Wn) {
                const float4* p = reinterpret_cast<const float4*>(
                    x + (((size_t)b * Hn + gr) * Wn + gc) * Cn);
                #pragma unroll
                for (int v = 0; v < 8; ++v) {
                    float4 q = p[v];
                    s = fmaf(q.x, q.x, s); s = fmaf(q.y, q.y, s);
                    s = fmaf(q.z, q.z, s); s = fmaf(q.w, q.w, s);
                }
            }
        }
        psq[tid] = s;
    } else {
        const int f = tid - 128;
        csq[f] = gcsq[f];
        sbeta[f] = beta[f];
    }
    __syncthreads();

    // ---- per-lane invariant ldmatrix offsets ----
    // A: row = lid&15 -> pixel p = wid*16+row; chunk = lid>>4 (k 0-7 / 8-15)
    const int arow  = lid & 15;
    const int achk  = lid >> 4;
    const int apx   = wid * 16 + arow;
    const uint32_t a_lane = ((uint32_t)(((apx >> 3) * 10 + (apx & 7)) * PX_PITCH
                                        + achk * 8)) * 2;
    const uint32_t ah_base = base + SM_XH + a_lane;
    // B: n = (lid&7) | ((lid&16)>>1) ; khalf = (lid>>3)&1
    const int bn    = (lid & 7) | ((lid & 16) >> 1);
    const int bkh   = (lid >> 3) & 1;
    const uint32_t b_lane = (uint32_t)(bn * B_ROW_B + bkh * 16);
    const uint32_t bh_base = base + SM_B + b_lane;

    float acc[16][4];
    #pragma unroll
    for (int i = 0; i < 16; ++i) {
        acc[i][0] = 0.f; acc[i][1] = 0.f; acc[i][2] = 0.f; acc[i][3] = 0.f;
    }

    #pragma unroll 1
    for (int pos = 0; pos < 9; ++pos) {
        const int tr = (pos * 11) >> 5;          // pos/3 for pos<9
        const int tc = pos - tr * 3;
        const uint32_t apos = ah_base + (uint32_t)((tr * 10 + tc) * PX_PITCH * 2);
        #pragma unroll
        for (int hs = 0; hs < 2; ++hs) {
            const int s = pos * 2 + hs;          // k-step: k0 = 16*s
            uint32_t ah[4], al[4];
            LDSM_X4(ah, apos + hs * 32);
            LDSM_X4(al, apos + hs * 32 + HALO_B);
            const uint32_t bs = bh_base + (uint32_t)(s * 32);
            #pragma unroll
            for (int g = 0; g < 8; ++g) {
                uint32_t bh[4], bl[4];
                const uint32_t ba = bs + (uint32_t)(g * 16 * B_ROW_B);
                LDSM_X4(bh, ba);
                LDSM_X4(bl, ba + B_HALF_B);
                MMA_BF16(acc[2 * g],     ah, bh[0], bh[1]);
                MMA_BF16(acc[2 * g + 1], ah, bh[2], bh[3]);
                MMA_BF16(acc[2 * g],     al, bh[0], bh[1]);
                MMA_BF16(acc[2 * g + 1], al, bh[2], bh[3]);
                MMA_BF16(acc[2 * g],     ah, bl[0], bl[1]);
                MMA_BF16(acc[2 * g + 1], ah, bl[2], bl[3]);
            }
        }
    }

    // ---- epilogue: D-frag thread t: rows t/4, t/4+8 ; cols 2*(t&3), +1 ----
    {
        const int quad = lid >> 2;
        const int tq   = lid & 3;
        const int p0 = wid * 16 + quad;
        const int p1 = p0 + 8;
        const int oh_0 = oh0 + (p0 >> 3), ow_0 = ow0 + (p0 & 7);
        const int oh_1 = oh0 + (p1 >> 3), ow_1 = ow0 + (p1 & 7);
        const bool v0 = (oh_0 < HoN) && (ow_0 < WoN);
        const bool v1 = (oh_1 < HoN) && (ow_1 < WoN);
        const float ps0 = psq[p0], ps1 = psq[p1];
        float* op0 = out + (((size_t)b * HoN + oh_0) * WoN + ow_0) * Fn;
        float* op1 = out + (((size_t)b * HoN + oh_1) * WoN + ow_1) * Fn;
        #pragma unroll
        for (int g2 = 0; g2 < 16; ++g2) {
            const int f = g2 * 8 + tq * 2;
            const float cs0 = csq[f], cs1 = csq[f + 1];
            const float bt0 = sbeta[f], bt1 = sbeta[f + 1];
            if (v0) {
                float2 r;
                r.x = __expf(-bt0 * (ps0 + cs0 + acc[g2][0]));
                r.y = __expf(-bt1 * (ps0 + cs1 + acc[g2][1]));
                *reinterpret_cast<float2*>(op0 + f) = r;
            }
            if (v1) {
                float2 r;
                r.x = __expf(-bt0 * (ps1 + cs0 + acc[g2][2]));
                r.y = __expf(-bt1 * (ps1 + cs1 + acc[g2][3]));
                *reinterpret_cast<float2*>(op1 + f) = r;
            }
        }
    }
}

extern "C" void kernel_launch(void* const* d_in, const int* in_sizes, int n_in,
                              void* d_out, int out_size)
{
    (void)in_sizes; (void)n_in; (void)out_size;
    const float* x    = (const float*)d_in[0];
    const float* ccs  = (const float*)d_in[1];
    const float* beta = (const float*)d_in[2];
    float* out = (float*)d_out;

    cudaFuncSetAttribute(rbf_mma_kernel,
                         cudaFuncAttributeMaxDynamicSharedMemorySize, SMEM_BYTES);

    rbf_prep_kernel<<<145, 256>>>(ccs);

    dim3 grid((WoN + TILE_W - 1) / TILE_W,   // 14
              (HoN + TILE_H - 1) / TILE_H,   // 7
              Bn);                           // 32
    rbf_mma_kernel<<<grid, THREADS, SMEM_BYTES>>>(x, beta, out);
}

// round 17
// speedup vs baseline: 2.7770x; 1.1548x over previous
#include <cuda_runtime.h>
#include <cuda_bf16.h>
#include <cstdint>
#include <cstddef>

// ---------------------------------------------------------------------------
// RBFolution via legacy tensor-core mma.sync (bf16, split 3-pass), sm_103-safe.
//   out[b,oh,ow,f] = exp(-beta[f] * (||p||^2 - 2 p.c_f + ||c_f||^2))
//   B=32,H=W=112,C=32,F=128,D=288 -> Ho=Wo=110.
//
// dot[px,f] = A[px,:].Bm[f,:],  Bm = -2*ccs^T, K=288 = 18 steps of k16.
// Split bf16: v = hi + lo; dot ~= Ah.Bh + Al.Bh + Ah.Bl (Al.Bl dropped).
// psq/csq full fp32. Measured rel_err ~1.7e-6.
//
// R17: CTA tile 16x16 px (256) x 128 f; warp = 32 px x 128 f (2 A-frags) so
// each B ldmatrix feeds 12 HMMA instead of 6 -> smem crossbar no longer paces
// the tensor pipe (R16: tensor 33%, L1 60%, 18 LDSM : 48 HMMA per warp-step;
// now 20 LDSM : 96 HMMA).
// ---------------------------------------------------------------------------

#define Bn 32
#define Hn 112
#define Wn 112
#define Cn 32
#define Fn 128
#define HoN 110
#define WoN 110
#define Dn 288

#define TILE_P 16                 // 16x16 pixel tile
#define THREADS 256

// B smem: [2 halves][128 f][pitch 296 bf16] ; 592B rows (ldmatrix conflict-free)
#define B_PITCH   296
#define B_ROW_B   (B_PITCH * 2)              // 592
#define B_HALF_B  (Fn * B_ROW_B)             // 75776
// halo: [18][18] px, pixel pitch 40 bf16 (80B) -> ldmatrix rows hit 8 banks
#define PX_PITCH  40
#define HALO_B    (18 * 18 * PX_PITCH * 2)   // 25920

#define SM_B      0
#define SM_XH     (2 * B_HALF_B)             // 151552
#define SM_XL     (SM_XH + HALO_B)           // 177472
#define SM_PSQ    (SM_XL + HALO_B)           // 203392 (256 f32)
#define SM_CSQ    (SM_PSQ + 1024)
#define SM_BETA   (SM_CSQ + 512)
#define SM_END    (SM_BETA + 512)            // 205440
#define SMEM_BYTES (SM_END + 1024)           // 206464

#define LDSM_X4(r, addr) \
    asm volatile("ldmatrix.sync.aligned.m8n8.x4.shared.b16 {%0,%1,%2,%3}, [%4];" \
        : "=r"((r)[0]), "=r"((r)[1]), "=r"((r)[2]), "=r"((r)[3]) : "r"(addr))

#define MMA_BF16(c, a, b0, b1) \
    asm volatile("mma.sync.aligned.m16n8k16.row.col.f32.bf16.bf16.f32 " \
        "{%0,%1,%2,%3}, {%4,%5,%6,%7}, {%8,%9}, {%0,%1,%2,%3};" \
        : "+f"((c)[0]), "+f"((c)[1]), "+f"((c)[2]), "+f"((c)[3]) \
        : "r"((a)[0]), "r"((a)[1]), "r"((a)[2]), "r"((a)[3]), "r"(b0), "r"(b1))

__device__ __forceinline__ uint32_t smem_to_u32(const void* p) {
    uint32_t a;
    asm("{ .reg .u64 t; cvta.to.shared.u64 t, %1; cvt.u32.u64 %0, t; }" : "=r"(a) : "l"(p));
    return a;
}

// ---- device globals ----
__device__ __align__(16) __nv_bfloat16 gB[2 * Fn * Dn];   // [half][f][k]
__device__ float gcsq[Fn];

// ===========================================================================
// Prep: Bm = -2*ccs^T split into (hi, lo); csq[f] = sum_d ccs[d][f]^2.
// ===========================================================================
__global__ void rbf_prep_kernel(const float* __restrict__ ccs)
{
    if (blockIdx.x == 144) {
        int f = threadIdx.x;
        if (f < Fn) {
            float s = 0.f;
            for (int d = 0; d < Dn; ++d) {
                float v = ccs[d * Fn + f];
                s = fmaf(v, v, s);
            }
            gcsq[f] = s;
        }
        return;
    }
    int idx = blockIdx.x * 256 + threadIdx.x;   // < 36864 = 128*288
    int f = idx / Dn;
    int k = idx - f * Dn;
    float val = -2.0f * ccs[k * Fn + f];
    __nv_bfloat16 h = __float2bfloat16(val);
    __nv_bfloat16 l = __float2bfloat16(val - __bfloat162float(h));
    gB[f * Dn + k] = h;
    gB[Fn * Dn + f * Dn + k] = l;
}

// ===========================================================================
// Main kernel: CTA = 256 px (16x16) x 128 f; warp w owns px [32w, 32w+32).
// ===========================================================================
__global__ void __launch_bounds__(THREADS, 1)
rbf_mma_kernel(const float* __restrict__ x,
               const float* __restrict__ beta,
               float* __restrict__ out)
{
    extern __shared__ char smraw[];
    const uint32_t base_raw = smem_to_u32(smraw);
    const uint32_t base = (base_raw + 1023) & ~1023u;
    char* sm = smraw + (base - base_raw);

    const int tid = threadIdx.x;
    const int wid = tid >> 5;
    const int lid = tid & 31;
    const int b   = blockIdx.z;
    const int oh0 = blockIdx.y * TILE_P;
    const int ow0 = blockIdx.x * TILE_P;

    float* psq   = reinterpret_cast<float*>(sm + SM_PSQ);
    float* csq   = reinterpret_cast<float*>(sm + SM_CSQ);
    float* sbeta = reinterpret_cast<float*>(sm + SM_BETA);

    // ---- copy split-B gmem -> smem with pitch expansion (9216 x 16B) ----
    {
        const float4* src = reinterpret_cast<const float4*>(gB);
        #pragma unroll 4
        for (int i = tid; i < 9216; i += THREADS) {
            int half = i / 4608;
            int rem  = i - half * 4608;
            int r    = rem / 36;            // 36 float4 per 288-elem row
            int v    = rem - r * 36;
            *reinterpret_cast<float4*>(sm + SM_B + half * B_HALF_B + r * B_ROW_B + v * 16)
                = src[i];
        }
    }

    // ---- load + split halo tile (18x18x32) into xh/xl ----
    {
        for (int i = tid; i < 2592; i += THREADS) {     // 2592 float4
            int pos = i >> 3;
            int v   = i & 7;
            int r   = pos / 18;
            int col = pos - r * 18;
            int gr  = oh0 + r, gc = ow0 + col;
            float4 val = make_float4(0.f, 0.f, 0.f, 0.f);
            if (gr < Hn && gc < Wn)
                val = *reinterpret_cast<const float4*>(
                    x + (((size_t)b * Hn + gr) * Wn + gc) * Cn + v * 4);
            __nv_bfloat16 h0 = __float2bfloat16(val.x), h1 = __float2bfloat16(val.y);
            __nv_bfloat16 h2 = __float2bfloat16(val.z), h3 = __float2bfloat16(val.w);
            __nv_bfloat16 l0 = __float2bfloat16(val.x - __bfloat162float(h0));
            __nv_bfloat16 l1 = __float2bfloat16(val.y - __bfloat162float(h1));
            __nv_bfloat16 l2 = __float2bfloat16(val.z - __bfloat162float(h2));
            __nv_bfloat16 l3 = __float2bfloat16(val.w - __bfloat162float(h3));
            uint2 hw, lw;
            hw.x = ((uint32_t)__bfloat16_as_ushort(h1) << 16) | __bfloat16_as_ushort(h0);
            hw.y = ((uint32_t)__bfloat16_as_ushort(h3) << 16) | __bfloat16_as_ushort(h2);
            lw.x = ((uint32_t)__bfloat16_as_ushort(l1) << 16) | __bfloat16_as_ushort(l0);
            lw.y = ((uint32_t)__bfloat16_as_ushort(l3) << 16) | __bfloat16_as_ushort(l2);
            const int off = ((r * 18 + col) * PX_PITCH + v * 4) * 2;
            *reinterpret_cast<uint2*>(sm + SM_XH + off) = hw;
            *reinterpret_cast<uint2*>(sm + SM_XL + off) = lw;
        }
    }

    // ---- psq: one pixel per thread (256 px, fp32 from gmem) ----
    {
        const int prow = tid >> 4, pcol = tid & 15;
        float s = 0.f;
        #pragma unroll
        for (int pos = 0; pos < 9; ++pos) {
            const int tr = pos / 3, tc = pos % 3;
            const int gr = oh0 + prow + tr, gc = ow0 + pcol + tc;
            if (gr < Hn && gc < Wn) {
                const float4* p = reinterpret_cast<const float4*>(
                    x + (((size_t)b * Hn + gr) * Wn + gc) * Cn);
                #pragma unroll
                for (int v = 0; v < 8; ++v) {
                    float4 q = p[v];
                    s = fmaf(q.x, q.x, s); s = fmaf(q.y, q.y, s);
                    s = fmaf(q.z, q.z, s); s = fmaf(q.w, q.w, s);
                }
            }
        }
        psq[tid] = s;
        if (tid < Fn) { csq[tid] = gcsq[tid]; sbeta[tid] = beta[tid]; }
    }
    __syncthreads();

    // ---- per-lane invariant ldmatrix offsets ----
    // A frag r (r=0,1): pixel p = wid*32 + r*16 + (lid&15) -> one full pixel
    // row of the 16-wide tile; chunk = lid>>4 selects k 0-7 / 8-15.
    const int arow  = lid & 15;
    const int achk  = lid >> 4;
    const int apx0  = wid * 32 + arow;           // frag 0
    const int apx1  = apx0 + 16;                 // frag 1
    const uint32_t aoff0 = ((uint32_t)(((apx0 >> 4) * 18 + (apx0 & 15)) * PX_PITCH
                                       + achk * 8)) * 2;
    const uint32_t aoff1 = ((uint32_t)(((apx1 >> 4) * 18 + (apx1 & 15)) * PX_PITCH
                                       + achk * 8)) * 2;
    const uint32_t ah0_base = base + SM_XH + aoff0;
    const uint32_t ah1_base = base + SM_XH + aoff1;
    // B: n = (lid&7) | ((lid&16)>>1) ; khalf = (lid>>3)&1
    const int bn    = (lid & 7) | ((lid & 16) >> 1);
    const int bkh   = (lid >> 3) & 1;
    const uint32_t bh_base = base + SM_B + (uint32_t)(bn * B_ROW_B + bkh * 16);

    float acc0[16][4], acc1[16][4];
    #pragma unroll
    for (int i = 0; i < 16; ++i) {
        acc0[i][0] = 0.f; acc0[i][1] = 0.f; acc0[i][2] = 0.f; acc0[i][3] = 0.f;
        acc1[i][0] = 0.f; acc1[i][1] = 0.f; acc1[i][2] = 0.f; acc1[i][3] = 0.f;
    }

    #pragma unroll 1
    for (int pos = 0; pos < 9; ++pos) {
        const int tr = (pos * 11) >> 5;          // pos/3 for pos<9
        const int tc = pos - tr * 3;
        const uint32_t posoff = (uint32_t)((tr * 18 + tc) * PX_PITCH * 2);
        #pragma unroll
        for (int hs = 0; hs < 2; ++hs) {
            const int s = pos * 2 + hs;          // k-step: k0 = 16*s
            uint32_t ah0[4], al0[4], ah1[4], al1[4];
            LDSM_X4(ah0, ah0_base + posoff + hs * 32);
            LDSM_X4(al0, ah0_base + posoff + hs * 32 + HALO_B);
            LDSM_X4(ah1, ah1_base + posoff + hs * 32);
            LDSM_X4(al1, ah1_base + posoff + hs * 32 + HALO_B);
            const uint32_t bs = bh_base + (uint32_t)(s * 32);
            #pragma unroll
            for (int g = 0; g < 8; ++g) {
                uint32_t bh[4], bl[4];
                const uint32_t ba = bs + (uint32_t)(g * 16 * B_ROW_B);
                LDSM_X4(bh, ba);
                LDSM_X4(bl, ba + B_HALF_B);
                MMA_BF16(acc0[2 * g],     ah0, bh[0], bh[1]);
                MMA_BF16(acc0[2 * g + 1], ah0, bh[2], bh[3]);
                MMA_BF16(acc1[2 * g],     ah1, bh[0], bh[1]);
                MMA_BF16(acc1[2 * g + 1], ah1, bh[2], bh[3]);
                MMA_BF16(acc0[2 * g],     al0, bh[0], bh[1]);
                MMA_BF16(acc0[2 * g + 1], al0, bh[2], bh[3]);
                MMA_BF16(acc1[2 * g],     al1, bh[0], bh[1]);
                MMA_BF16(acc1[2 * g + 1], al1, bh[2], bh[3]);
                MMA_BF16(acc0[2 * g],     ah0, bl[0], bl[1]);
                MMA_BF16(acc0[2 * g + 1], ah0, bl[2], bl[3]);
                MMA_BF16(acc1[2 * g],     ah1, bl[0], bl[1]);
                MMA_BF16(acc1[2 * g + 1], ah1, bl[2], bl[3]);
            }
        }
    }

    // ---- epilogue: D-frag thread t: rows t/4, t/4+8 ; cols 2*(t&3), +1 ----
    {
        const int quad = lid >> 2;
        const int tq   = lid & 3;
        #pragma unroll
        for (int frag = 0; frag < 2; ++frag) {
            float (*acc)[4] = frag ? acc1 : acc0;
            const int p0 = wid * 32 + frag * 16 + quad;
            const int p1 = p0 + 8;
            const int oh_0 = oh0 + (p0 >> 4), ow_0 = ow0 + (p0 & 15);
            const int oh_1 = oh0 + (p1 >> 4), ow_1 = ow0 + (p1 & 15);
            const bool v0 = (oh_0 < HoN) && (ow_0 < WoN);
            const bool v1 = (oh_1 < HoN) && (ow_1 < WoN);
            const float ps0 = psq[p0], ps1 = psq[p1];
            float* op0 = out + (((size_t)b * HoN + oh_0) * WoN + ow_0) * Fn;
            float* op1 = out + (((size_t)b * HoN + oh_1) * WoN + ow_1) * Fn;
            #pragma unroll
            for (int g2 = 0; g2 < 16; ++g2) {
                const int f = g2 * 8 + tq * 2;
                const float cs0 = csq[f], cs1 = csq[f + 1];
                const float bt0 = sbeta[f], bt1 = sbeta[f + 1];
                if (v0) {
                    float2 r;
                    r.x = __expf(-bt0 * (ps0 + cs0 + acc[g2][0]));
                    r.y = __expf(-bt1 * (ps0 + cs1 + acc[g2][1]));
                    *reinterpret_cast<float2*>(op0 + f) = r;
                }
                if (v1) {
                    float2 r;
                    r.x = __expf(-bt0 * (ps1 + cs0 + acc[g2][2]));
                    r.y = __expf(-bt1 * (ps1 + cs1 + acc[g2][3]));
                    *reinterpret_cast<float2*>(op1 + f) = r;
                }
            }
        }
    }
}

extern "C" void kernel_launch(void* const* d_in, const int* in_sizes, int n_in,
                              void* d_out, int out_size)
{
    (void)in_sizes; (void)n_in; (void)out_size;
    const float* x    = (const float*)d_in[0];
    const float* ccs  = (const float*)d_in[1];
    const float* beta = (const float*)d_in[2];
    float* out = (float*)d_out;

    cudaFuncSetAttribute(rbf_mma_kernel,
                         cudaFuncAttributeMaxDynamicSharedMemorySize, SMEM_BYTES);

    rbf_prep_kernel<<<145, 256>>>(ccs);

    dim3 grid((WoN + TILE_P - 1) / TILE_P,   // 7
              (HoN + TILE_P - 1) / TILE_P,   // 7
              Bn);                           // 32
    rbf_mma_kernel<<<grid, THREADS, SMEM_BYTES>>>(x, beta, out);
}